// round 7
// baseline (speedup 1.0000x reference)
#include <cuda_runtime.h>
#include <cuda_bf16.h>
#include <stdint.h>

// ===========================================================================
// Helpers (baseline PTX only — no sm_100a-gated instructions)
// ===========================================================================
__device__ __forceinline__ uint32_t smem_u32(const void* p) {
    uint32_t a;
    asm("{ .reg .u64 t; cvta.to.shared.u64 t, %1; cvt.u32.u64 %0, t; }"
        : "=r"(a) : "l"(p));
    return a;
}
#define CP_COMMIT() asm volatile("cp.async.commit_group;" ::: "memory")
#define CP_WAIT2()  asm volatile("cp.async.wait_group 2;" ::: "memory")
__device__ __forceinline__ void cp16(uint32_t saddr, const void* g) {
    asm volatile("cp.async.cg.shared.global [%0], [%1], 16;" :: "r"(saddr), "l"(g));
}
__device__ __forceinline__ void ldm_x4(uint32_t& r0, uint32_t& r1,
                                       uint32_t& r2, uint32_t& r3, uint32_t a) {
    asm volatile("ldmatrix.sync.aligned.m8n8.x4.shared.b16 {%0,%1,%2,%3}, [%4];"
                 : "=r"(r0), "=r"(r1), "=r"(r2), "=r"(r3) : "r"(a));
}
__device__ __forceinline__ void hmma(float& d0, float& d1, float& d2, float& d3,
                                     uint32_t a0, uint32_t a1, uint32_t a2, uint32_t a3,
                                     uint32_t b0, uint32_t b1) {
    asm volatile("mma.sync.aligned.m16n8k16.row.col.f32.bf16.bf16.f32 "
                 "{%0,%1,%2,%3},{%4,%5,%6,%7},{%8,%9},{%0,%1,%2,%3};"
                 : "+f"(d0), "+f"(d1), "+f"(d2), "+f"(d3)
                 : "r"(a0), "r"(a1), "r"(a2), "r"(a3), "r"(b0), "r"(b1));
}
__device__ __forceinline__ uint32_t sw128(uint32_t off) {
    return off ^ ((off >> 3) & 0x70);
}

// ===========================================================================
// Index tables. Valid (i, ph): i2 = i + 2*ph - 14 in [0,7). 25 combos/axis.
// Inverse map: (i1, i2) valid iff (i2-i1) even; uIdx = c_base[i1] + (i2>>1).
// ===========================================================================
__constant__ int c_I   [25] = {0,0,0,0, 1,1,1, 2,2,2,2, 3,3,3, 4,4,4,4, 5,5,5, 6,6,6,6};
__constant__ int c_PH  [25] = {7,8,9,10, 7,8,9, 6,7,8,9, 6,7,8, 5,6,7,8, 5,6,7, 4,5,6,7};
__constant__ int c_base[7]  = {0, 4, 7, 11, 14, 18, 21};

static const int B_  = 1024;
static const int KC_ = 640;
__device__ __nv_bfloat16 g_Xh [B_ * KC_];
__device__ __nv_bfloat16 g_Xl [B_ * KC_];
__device__ __nv_bfloat16 g_W1h[1024 * KC_];
__device__ __nv_bfloat16 g_W1l[1024 * KC_];
__device__ __nv_bfloat16 g_W2h[1024 * 1024];
__device__ __nv_bfloat16 g_W2l[1024 * 1024];
__device__ __nv_bfloat16 g_H1h[B_ * 1024];
__device__ __nv_bfloat16 g_H1l[B_ * 1024];
__device__ float         g_H2 [B_ * 1024];

__device__ __forceinline__ void split_bf16(float x, __nv_bfloat16& h, __nv_bfloat16& l) {
    h = __float2bfloat16(x);
    l = __float2bfloat16(x - __bfloat162float(h));
}

// ===========================================================================
// Correlation via HMMA Gram matrix. One CTA (256 thr) per RoI.
// SMEM: S1 [64 pix][512 bf16] (hi cols 0..255, lo 256..511), S2 same,
// fp32 staging [256][49]. Rows 49..63 zeroed (outputs there discarded).
// G = P1 * P2^T over virtual K' = 768 ([hi|lo|hi] x [hi|hi|lo]).
// Epilogue maps G(pix1,pix2) -> feature t, emits hi/lo bf16.
// ===========================================================================
#define CORR_SMEM (65536 * 2 + 49 * 256 * 4)   // 181248 B

__global__ __launch_bounds__(256) void corr_mma_kernel(
    const float* __restrict__ p1, const float* __restrict__ p2,
    __nv_bfloat16* __restrict__ Xh, __nv_bfloat16* __restrict__ Xl)
{
    extern __shared__ char smem[];
    const uint32_t sb = smem_u32(smem);
    const uint32_t S1 = sb;
    const uint32_t S2 = sb + 65536;
    float* stage = (float*)(smem + 131072);

    const int b = blockIdx.x;
    const int tid = threadIdx.x;
    const int lane = tid & 31;
    const int w = tid >> 5;

    // Zero pad rows 49..63 of both bf16 buffers (1024 B per row).
    {
        uint32_t* z = (uint32_t*)smem;
        for (int i = tid; i < 2 * 15 * 256; i += 256) {
            int buf = i >= 15 * 256;
            int j = i - buf * 15 * 256;
            z[buf * 16384 + (49 * 256) + j] = 0;   // 49*1024B = 49*256 words
        }
    }

    const float* g1 = p1 + (size_t)b * 12544;
    const float* g2 = p2 + (size_t)b * 12544;

    // ---- patch1: stage (coalesced) then transpose-convert into S1 ----
    #pragma unroll 7
    for (int q = 0; q < 49; q++) stage[q * 256 + tid] = g1[q * 256 + tid];
    __syncthreads();
    #pragma unroll 7
    for (int pix = 0; pix < 49; pix++) {
        float x = stage[tid * 49 + pix];          // [c=tid][pix]; stride-49: conflict-free
        __nv_bfloat16 h, l; split_bf16(x, h, l);
        uint32_t swz = ((uint32_t)pix & 7) << 4;
        char* rowp = smem + pix * 1024;
        *(__nv_bfloat16*)(rowp + (((uint32_t)tid * 2) ^ swz))        = h;
        *(__nv_bfloat16*)(rowp + ((512u + (uint32_t)tid * 2) ^ swz)) = l;
    }
    __syncthreads();
    // ---- patch2 -> S2 ----
    #pragma unroll 7
    for (int q = 0; q < 49; q++) stage[q * 256 + tid] = g2[q * 256 + tid];
    __syncthreads();
    #pragma unroll 7
    for (int pix = 0; pix < 49; pix++) {
        float x = stage[tid * 49 + pix];
        __nv_bfloat16 h, l; split_bf16(x, h, l);
        uint32_t swz = ((uint32_t)pix & 7) << 4;
        char* rowp = smem + 65536 + pix * 1024;
        *(__nv_bfloat16*)(rowp + (((uint32_t)tid * 2) ^ swz))        = h;
        *(__nv_bfloat16*)(rowp + ((512u + (uint32_t)tid * 2) ^ swz)) = l;
    }
    __syncthreads();

    // ---- Gram MMA: warp w -> rows (w&3)*16, cols (w>>2)*32 ----
    const int rowA = (w & 3) * 16 + (lane & 15);
    const uint32_t aRow  = S1 + (uint32_t)rowA * 1024;
    const uint32_t aXor  = ((uint32_t)rowA & 7) << 4;
    const uint32_t aHalf = ((uint32_t)(lane >> 4) & 1) << 4;

    const int rowB0 = (w >> 2) * 32 + (lane & 7) + ((lane >> 4) << 3);
    const uint32_t bXor  = ((uint32_t)rowB0 & 7) << 4;     // +16 keeps low 3 row bits
    const uint32_t bHalf = ((uint32_t)(lane >> 3) & 1) << 4;
    const uint32_t bRow0 = S2 + (uint32_t)rowB0 * 1024;
    const uint32_t bRow1 = bRow0 + 16 * 1024;

    float acc[4][4];
    #pragma unroll
    for (int nt = 0; nt < 4; nt++)
        #pragma unroll
        for (int q = 0; q < 4; q++) acc[nt][q] = 0.f;

    #pragma unroll
    for (int term = 0; term < 3; term++) {
        const uint32_t ab = (term == 1) ? 512u : 0u;
        const uint32_t bb = (term == 2) ? 512u : 0u;
        #pragma unroll
        for (int ks = 0; ks < 16; ks++) {
            uint32_t a0, a1, a2, a3;
            ldm_x4(a0, a1, a2, a3, aRow + ((ab + ks * 32 + aHalf) ^ aXor));
            uint32_t ca = (bb + ks * 32 + bHalf) ^ bXor;
            uint32_t b0, b1, b2, b3;
            ldm_x4(b0, b1, b2, b3, bRow0 + ca);
            hmma(acc[0][0], acc[0][1], acc[0][2], acc[0][3], a0, a1, a2, a3, b0, b1);
            hmma(acc[1][0], acc[1][1], acc[1][2], acc[1][3], a0, a1, a2, a3, b2, b3);
            ldm_x4(b0, b1, b2, b3, bRow1 + ca);
            hmma(acc[2][0], acc[2][1], acc[2][2], acc[2][3], a0, a1, a2, a3, b0, b1);
            hmma(acc[3][0], acc[3][1], acc[3][2], acc[3][3], a0, a1, a2, a3, b2, b3);
        }
    }

    // ---- epilogue: G(r, c) -> t = (base[i1]+(i2>>1))*25 + base[j1]+(j2>>1) ----
    __nv_bfloat16* xh = Xh + (size_t)b * KC_;
    __nv_bfloat16* xl = Xl + (size_t)b * KC_;
    auto emit = [&](int r, int c, float v) {
        if (r >= 49 || c >= 49) return;
        int i1 = r / 7, j1 = r - i1 * 7;
        int i2 = c / 7, j2 = c - i2 * 7;
        if (((i2 ^ i1) & 1) || ((j2 ^ j1) & 1)) return;
        int t = (c_base[i1] + (i2 >> 1)) * 25 + c_base[j1] + (j2 >> 1);
        __nv_bfloat16 h, l; split_bf16(v, h, l);
        xh[t] = h; xl[t] = l;
    };
    const int er = (w & 3) * 16 + (lane >> 2);
    #pragma unroll
    for (int nt = 0; nt < 4; nt++) {
        const int ec = (w >> 2) * 32 + nt * 8 + (lane & 3) * 2;
        emit(er,     ec,     acc[nt][0]);
        emit(er,     ec + 1, acc[nt][1]);
        emit(er + 8, ec,     acc[nt][2]);
        emit(er + 8, ec + 1, acc[nt][3]);
    }
    // zero padding features 625..639
    if (tid < 15) {
        xh[625 + tid] = __float2bfloat16(0.f);
        xl[625 + tid] = __float2bfloat16(0.f);
    }
}

// ===========================================================================
// Gather the 625 used W1 columns -> hi/lo bf16 [n][640]
// ===========================================================================
__global__ __launch_bounds__(640) void gather_w1_kernel(
    const float* __restrict__ W1,
    __nv_bfloat16* __restrict__ Wh, __nv_bfloat16* __restrict__ Wl)
{
    const int n = blockIdx.x, k = threadIdx.x;
    float v_out = 0.f;
    if (k < 625) {
        int u = k / 25, v = k - u * 25;
        int feat = (c_PH[u] * 16 + c_PH[v]) * 49 + c_I[u] * 7 + c_I[v];
        v_out = W1[n * 12544 + feat];
    }
    __nv_bfloat16 h, l; split_bf16(v_out, h, l);
    Wh[n * KC_ + k] = h; Wl[n * KC_ + k] = l;
}

// ===========================================================================
// Split W2 fp32 -> hi/lo bf16
// ===========================================================================
__global__ __launch_bounds__(256) void split_w2_kernel(
    const float* __restrict__ W2,
    __nv_bfloat16* __restrict__ Wh, __nv_bfloat16* __restrict__ Wl)
{
    const int row = blockIdx.x;
    const int t = threadIdx.x;
    float4 v = *(const float4*)(W2 + row * 1024 + t * 4);
    __nv_bfloat16 h0,l0,h1,l1,h2,l2,h3,l3;
    split_bf16(v.x, h0, l0); split_bf16(v.y, h1, l1);
    split_bf16(v.z, h2, l2); split_bf16(v.w, h3, l3);
    __nv_bfloat162* ph = (__nv_bfloat162*)(Wh + row * 1024 + t * 4);
    __nv_bfloat162* pl = (__nv_bfloat162*)(Wl + row * 1024 + t * 4);
    ph[0] = __nv_bfloat162(h0, h1); ph[1] = __nv_bfloat162(h2, h3);
    pl[0] = __nv_bfloat162(l0, l1); pl[1] = __nv_bfloat162(l2, l3);
}

// ===========================================================================
// HMMA bf16-split GEMM: C = relu(A * Bt^T + bias)  (unchanged from R4)
// ===========================================================================
#define NS 3
#define STAGE_BYTES (128 * 128 + 64 * 128)

template<int OUT_BF16>
__global__ __launch_bounds__(256, 2) void hmma_fc_kernel(
    const __nv_bfloat16* __restrict__ Ah, const __nv_bfloat16* __restrict__ Al,
    const __nv_bfloat16* __restrict__ Bh, const __nv_bfloat16* __restrict__ Bl,
    const float* __restrict__ bias,
    float* __restrict__ Cf, __nv_bfloat16* __restrict__ Ch,
    __nv_bfloat16* __restrict__ Cl, int K)
{
    extern __shared__ char smem[];
    const uint32_t sbase = smem_u32(smem);

    const int tid  = threadIdx.x;
    const int lane = tid & 31;
    const int wid  = tid >> 5;
    const int wm   = wid & 3;
    const int wn   = wid >> 2;
    const int m0 = blockIdx.y * 128, n0 = blockIdx.x * 64;

    const int cpt = K >> 6;
    const int nch = 3 * cpt;
    const size_t krow = (size_t)K * 2;

    auto fill = [&](int chunk, int stage) {
        int term = (chunk >= 2 * cpt) ? 2 : (chunk >= cpt ? 1 : 0);
        int cc = chunk - term * cpt;
        const __nv_bfloat16* As = (term == 1) ? Al : Ah;
        const __nv_bfloat16* Bs = (term == 2) ? Bl : Bh;
        const char* ag = (const char*)As + (size_t)m0 * krow + cc * 128;
        const char* bg = (const char*)Bs + (size_t)n0 * krow + cc * 128;
        uint32_t da = sbase + stage * STAGE_BYTES;
        uint32_t db = da + 128 * 128;
        #pragma unroll
        for (int q = 0; q < 4; q++) {
            int i = tid + q * 256;
            int row = i >> 3, c = (i & 7) << 4;
            cp16(da + sw128((uint32_t)(row << 7) + c), ag + (size_t)row * krow + c);
        }
        #pragma unroll
        for (int q = 0; q < 2; q++) {
            int i = tid + q * 256;
            int row = i >> 3, c = (i & 7) << 4;
            cp16(db + sw128((uint32_t)(row << 7) + c), bg + (size_t)row * krow + c);
        }
    };

    float acc[2][4][4];
    #pragma unroll
    for (int mt = 0; mt < 2; mt++)
        #pragma unroll
        for (int nt = 0; nt < 4; nt++)
            #pragma unroll
            for (int q = 0; q < 4; q++) acc[mt][nt][q] = 0.f;

    fill(0, 0); CP_COMMIT();
    fill(1, 1); CP_COMMIT();

    const int arow_base = wm * 32 + (lane & 15);
    const int acol_half = ((lane >> 4) & 1) << 4;
    const int brow_base = wn * 32 + (lane & 7) + ((lane >> 4) << 3);
    const int bcol_half = (((lane >> 3) & 1)) << 4;

    for (int ch = 0; ch < nch; ch++) {
        if (ch + 2 < nch) fill(ch + 2, (ch + 2) % NS);
        CP_COMMIT();
        CP_WAIT2();
        __syncthreads();

        const uint32_t sa = sbase + (ch % NS) * STAGE_BYTES;
        const uint32_t sb2 = sa + 128 * 128;

        #pragma unroll
        for (int ks = 0; ks < 4; ks++) {
            uint32_t a[2][4], b[2][4];
            #pragma unroll
            for (int mt = 0; mt < 2; mt++) {
                int row = arow_base + mt * 16;
                uint32_t off = (uint32_t)(row << 7) + (ks * 32 + acol_half);
                ldm_x4(a[mt][0], a[mt][1], a[mt][2], a[mt][3],
                       sa + (off ^ (((uint32_t)row & 7) << 4)));
            }
            #pragma unroll
            for (int np = 0; np < 2; np++) {
                int row = brow_base + np * 16;
                uint32_t off = (uint32_t)(row << 7) + (ks * 32 + bcol_half);
                ldm_x4(b[np][0], b[np][1], b[np][2], b[np][3],
                       sb2 + (off ^ (((uint32_t)row & 7) << 4)));
            }
            #pragma unroll
            for (int mt = 0; mt < 2; mt++)
                #pragma unroll
                for (int np = 0; np < 2; np++) {
                    hmma(acc[mt][np*2][0],   acc[mt][np*2][1],
                         acc[mt][np*2][2],   acc[mt][np*2][3],
                         a[mt][0], a[mt][1], a[mt][2], a[mt][3],
                         b[np][0], b[np][1]);
                    hmma(acc[mt][np*2+1][0], acc[mt][np*2+1][1],
                         acc[mt][np*2+1][2], acc[mt][np*2+1][3],
                         a[mt][0], a[mt][1], a[mt][2], a[mt][3],
                         b[np][2], b[np][3]);
                }
        }
        __syncthreads();
    }

    #pragma unroll
    for (int mt = 0; mt < 2; mt++) {
        int row = m0 + wm * 32 + mt * 16 + (lane >> 2);
        #pragma unroll
        for (int nt = 0; nt < 4; nt++) {
            int col = n0 + wn * 32 + nt * 8 + (lane & 3) * 2;
            float2 bz = *(const float2*)&bias[col];
            float x0 = fmaxf(acc[mt][nt][0] + bz.x, 0.f);
            float y0 = fmaxf(acc[mt][nt][1] + bz.y, 0.f);
            float x1 = fmaxf(acc[mt][nt][2] + bz.x, 0.f);
            float y1 = fmaxf(acc[mt][nt][3] + bz.y, 0.f);
            if (OUT_BF16) {
                __nv_bfloat16 h, l, h2, l2;
                split_bf16(x0, h, l); split_bf16(y0, h2, l2);
                ((__nv_bfloat162*)Ch)[(size_t)row * 512 + (col >> 1)] = __nv_bfloat162(h, h2);
                ((__nv_bfloat162*)Cl)[(size_t)row * 512 + (col >> 1)] = __nv_bfloat162(l, l2);
                split_bf16(x1, h, l); split_bf16(y1, h2, l2);
                ((__nv_bfloat162*)Ch)[(size_t)(row + 8) * 512 + (col >> 1)] = __nv_bfloat162(h, h2);
                ((__nv_bfloat162*)Cl)[(size_t)(row + 8) * 512 + (col >> 1)] = __nv_bfloat162(l, l2);
            } else {
                *(float2*)&Cf[(size_t)row * 1024 + col]       = make_float2(x0, y0);
                *(float2*)&Cf[(size_t)(row + 8) * 1024 + col] = make_float2(x1, y1);
            }
        }
    }
}

// ===========================================================================
// FC3: one warp per (b, o)
// ===========================================================================
__global__ __launch_bounds__(128) void fc3_kernel(
    const float* __restrict__ H2, const float* __restrict__ W3,
    const float* __restrict__ b3, float* __restrict__ out)
{
    const int b = blockIdx.x;
    const int o = threadIdx.x >> 5;
    const int l = threadIdx.x & 31;
    const float4* h = (const float4*)(H2 + b * 1024);
    const float4* w = (const float4*)(W3 + o * 1024);
    float s = 0.f;
    #pragma unroll
    for (int i = 0; i < 8; i++) {
        float4 hv = h[i * 32 + l];
        float4 wv = w[i * 32 + l];
        s = fmaf(hv.x, wv.x, s); s = fmaf(hv.y, wv.y, s);
        s = fmaf(hv.z, wv.z, s); s = fmaf(hv.w, wv.w, s);
    }
    #pragma unroll
    for (int off = 16; off; off >>= 1)
        s += __shfl_xor_sync(0xFFFFFFFFu, s, off);
    if (l == 0) out[b * 4 + o] = s + b3[o];
}

// ===========================================================================
extern "C" void kernel_launch(void* const* d_in, const int* in_sizes, int n_in,
                              void* d_out, int out_size)
{
    (void)in_sizes; (void)n_in; (void)out_size;
    const float* p1 = (const float*)d_in[0];
    const float* p2 = (const float*)d_in[1];
    const float* W1 = (const float*)d_in[2];
    const float* b1 = (const float*)d_in[3];
    const float* W2 = (const float*)d_in[4];
    const float* b2 = (const float*)d_in[5];
    const float* W3 = (const float*)d_in[6];
    const float* b3 = (const float*)d_in[7];
    float* out = (float*)d_out;

    __nv_bfloat16 *Xh, *Xl, *W1h, *W1l, *W2h, *W2l, *H1h, *H1l;
    float* H2;
    cudaGetSymbolAddress((void**)&Xh,  g_Xh);
    cudaGetSymbolAddress((void**)&Xl,  g_Xl);
    cudaGetSymbolAddress((void**)&W1h, g_W1h);
    cudaGetSymbolAddress((void**)&W1l, g_W1l);
    cudaGetSymbolAddress((void**)&W2h, g_W2h);
    cudaGetSymbolAddress((void**)&W2l, g_W2l);
    cudaGetSymbolAddress((void**)&H1h, g_H1h);
    cudaGetSymbolAddress((void**)&H1l, g_H1l);
    cudaGetSymbolAddress((void**)&H2,  g_H2);

    cudaFuncSetAttribute(corr_mma_kernel,
                         cudaFuncAttributeMaxDynamicSharedMemorySize, CORR_SMEM);
    const int gemm_smem = NS * STAGE_BYTES;
    cudaFuncSetAttribute(hmma_fc_kernel<1>,
                         cudaFuncAttributeMaxDynamicSharedMemorySize, gemm_smem);
    cudaFuncSetAttribute(hmma_fc_kernel<0>,
                         cudaFuncAttributeMaxDynamicSharedMemorySize, gemm_smem);

    corr_mma_kernel<<<1024, 256, CORR_SMEM>>>(p1, p2, Xh, Xl);
    gather_w1_kernel<<<1024, 640>>>(W1, W1h, W1l);
    split_w2_kernel<<<1024, 256>>>(W2, W2h, W2l);

    dim3 grid(16, 8);
    hmma_fc_kernel<1><<<grid, 256, gemm_smem>>>(Xh, Xl, W1h, W1l, b1,
                                                nullptr, H1h, H1l, KC_);
    hmma_fc_kernel<0><<<grid, 256, gemm_smem>>>(H1h, H1l, W2h, W2l, b2,
                                                H2, nullptr, nullptr, 1024);
    fc3_kernel<<<1024, 128>>>(H2, W3, b3, out);
}